// round 11
// baseline (speedup 1.0000x reference)
#include <cuda_runtime.h>
#include <cuda_bf16.h>
#include <math.h>

#define NBLK 128
#define NTHR 512
#define Bn 64
#define Sn 512
#define BH 32768

typedef unsigned u32;
typedef unsigned long long u64;

// output section offsets (floats)
#define O_HID   0ull
#define O_HMU   16777216ull
#define O_HSTD  33587200ull
#define O_CMU   50397184ull
#define O_CSTD  67207168ull
#define O_HT    84017152ull
#define O_CT    84049920ull

// global state (bf16 hi/lo splits; [b][*] layouts)
__device__ __nv_bfloat16 g_xh[(size_t)Bn*Sn*512];   // [b][s][k]
__device__ __nv_bfloat16 g_xl[(size_t)Bn*Sn*512];
__device__ __nv_bfloat16 g_hh[BH], g_hl[BH];        // sampled h [b][n]
__device__ __nv_bfloat16 g_nhh[BH], g_nhl[BH];      // h_new
__device__ __nv_bfloat16 g_nch[BH], g_ncl[BH];      // c_new
__device__ float g_cs[BH];                          // sampled c (fp32)
__device__ unsigned g_cnt = 0;
__device__ volatile unsigned g_gen = 0;

__device__ __forceinline__ void grid_bar() {
    __syncthreads();
    if (threadIdx.x == 0) {
        __threadfence();
        unsigned gen = g_gen;
        if (atomicAdd(&g_cnt, 1u) == NBLK - 1) {
            g_cnt = 0;
            __threadfence();
            g_gen = gen + 1;
        } else {
            while (g_gen == gen) { }
            __threadfence();
        }
    }
    __syncthreads();
}

__device__ __forceinline__ float sigm(float v) { return 1.0f / (1.0f + expf(-v)); }
__device__ __forceinline__ float softplus(float v) {
    return fmaxf(v, 0.0f) + log1pf(expf(-fabsf(v)));
}

// ---------- PTX helpers (sm_80+, legal on compute_100) ----------
__device__ __forceinline__ u32 smem_u32(const void* p) {
    u32 a;
    asm("{ .reg .u64 t; cvta.to.shared.u64 t, %1; cvt.u32.u64 %0, t; }" : "=r"(a) : "l"(p));
    return a;
}
__device__ __forceinline__ void cpa16(u32 dst, const void* src) {
    asm volatile("cp.async.cg.shared.global [%0], [%1], 16;" :: "r"(dst), "l"(src));
}
__device__ __forceinline__ void cpa_mbar_arrive(u32 mbar) {
    asm volatile("cp.async.mbarrier.arrive.noinc.shared.b64 [%0];" :: "r"(mbar) : "memory");
}
__device__ __forceinline__ void mbar_init(u32 a, u32 cnt) {
    asm volatile("mbarrier.init.shared.b64 [%0], %1;" :: "r"(a), "r"(cnt) : "memory");
}
__device__ __forceinline__ void mbar_arrive(u32 a) {
    asm volatile("mbarrier.arrive.shared.b64 _, [%0];" :: "r"(a) : "memory");
}
__device__ __forceinline__ void mbar_wait(u32 a, u32 parity) {
    asm volatile(
        "{\n\t.reg .pred P;\n\t"
        "WL%=:\n\t"
        "mbarrier.try_wait.parity.acquire.cta.shared::cta.b64 P, [%0], %1, 0x989680;\n\t"
        "@P bra.uni WD%=;\n\t"
        "bra.uni WL%=;\n\t"
        "WD%=:\n\t}"
        :: "r"(a), "r"(parity) : "memory");
}
__device__ __forceinline__ void ldm4(u32* r, u32 addr) {
    asm volatile("ldmatrix.sync.aligned.m8n8.x4.shared.b16 {%0,%1,%2,%3}, [%4];"
                 : "=r"(r[0]), "=r"(r[1]), "=r"(r[2]), "=r"(r[3]) : "r"(addr));
}
__device__ __forceinline__ void lds2(u32& x, u32& y, u32 a) {
    asm volatile("ld.shared.v2.b32 {%0,%1}, [%2];" : "=r"(x), "=r"(y) : "r"(a));
}
__device__ __forceinline__ void mma16816(float* d, const u32* a, u32 b0, u32 b1) {
    asm volatile(
        "mma.sync.aligned.m16n8k16.row.col.f32.bf16.bf16.f32 "
        "{%0,%1,%2,%3}, {%4,%5,%6,%7}, {%8,%9}, {%0,%1,%2,%3};"
        : "+f"(d[0]), "+f"(d[1]), "+f"(d[2]), "+f"(d[3])
        : "r"(a[0]), "r"(a[1]), "r"(a[2]), "r"(a[3]), "r"(b0), "r"(b1));
}
__device__ __forceinline__ u32 hpair(__nv_bfloat16 a, __nv_bfloat16 b) {
    unsigned short ua = *(unsigned short*)&a, ub = *(unsigned short*)&b;
    return (u32)ua | ((u32)ub << 16);
}

// SMEM map (bytes)
#define SO_W1H  0
#define SO_W1L  32768
#define SO_W2H  65536
#define SO_W2L  81920
#define SO_A    98304
#define GBUF    13824      // per group: 3 stages x 4608 (hi 16x144 + lo 16x144)
#define SO_DP   208896     // 2 x 64 x 18 f32
#define SO_B1   218112
#define SO_MB   218176     // 24 x (full,empty) = 384B
#define SMEM_BYTES 218560

// one-time x split
__global__ void xsplit_kernel(const float* __restrict__ x) {
    size_t i = (size_t)blockIdx.x * 256 + threadIdx.x;
    float v = x[i];
    __nv_bfloat16 hi = __float2bfloat16(v);
    g_xh[i] = hi;
    g_xl[i] = __float2bfloat16(v - __bfloat162float(hi));
}

__global__ __launch_bounds__(NTHR, 1)
void rglstm(const float* __restrict__ W_ih, const float* __restrict__ W_hh,
            const float* __restrict__ b_ih, const float* __restrict__ b_hh,
            const float* __restrict__ W_hg, const float* __restrict__ W_cg,
            const float* __restrict__ eps_h, const float* __restrict__ eps_c,
            float* __restrict__ out)
{
    extern __shared__ char smem8[];
    float* sB1 = (float*)(smem8 + SO_B1);
    float* Dp  = (float*)(smem8 + SO_DP);     // [2][64][18]

    const int tid  = threadIdx.x;
    const int wid  = tid >> 5;
    const int lane = tid & 31;
    const int cb   = blockIdx.x;
    const bool isH = cb < 64;
    const int n0_1 = cb << 2;
    const int n0_2 = (cb & 63) << 3;

    const u32 sb  = smem_u32(smem8);
    const u32 sbA = sb + SO_A;

    // warp roles: mt = m-tile (16 rows), nt = n-half (8 cols), kh = k-half of chunk
    const int mt = wid & 3;
    const int nt = (wid >> 2) & 1;
    const int kh = wid >> 3;
    const int gid = mt | (kh << 2);           // 8 groups; producer = nt==0 warp
    const bool producer = (nt == 0);
    const u32 gBase = sbA + (u32)gid * GBUF;

    // ldmatrix per-lane offset within a stage tile (16 rows x 144B, hi; lo at +2304)
    const u32 aOff = (u32)((lane & 15) * 144 + ((lane >> 4) & 1) * 16);

    // producer-load geometry: lane -> (row 0..15, half 0..1) of 64-k slice
    const int lrow = lane >> 1;
    const int half = lane & 1;

    // ---- weight fragments (hi/lo), fragment-order SMEM ----
    for (int i = tid; i < 4096; i += NTHR) {          // W1: 128 frags x 32 lanes
        int fr = i >> 5, l = i & 31;
        int ktg = fr >> 1, ntw = fr & 1;
        int nl = ntw * 8 + (l >> 2);
        int gcol = (nl >> 2) * 512 + n0_1 + (nl & 3);
        int k0 = ktg * 16 + 2 * (l & 3);
        const float* base = (k0 < 512) ? (W_ih + gcol * 512) : (W_hh + gcol * 512 - 512);
        float w00 = base[k0], w01 = base[k0 + 1], w08 = base[k0 + 8], w09 = base[k0 + 9];
        __nv_bfloat16 h00 = __float2bfloat16(w00), h01 = __float2bfloat16(w01);
        __nv_bfloat16 h08 = __float2bfloat16(w08), h09 = __float2bfloat16(w09);
        u32 off = (u32)(fr * 256 + l * 8);
        *(u32*)(smem8 + SO_W1H + off)     = hpair(h00, h01);
        *(u32*)(smem8 + SO_W1H + off + 4) = hpair(h08, h09);
        *(u32*)(smem8 + SO_W1L + off)     = hpair(__float2bfloat16(w00 - __bfloat162float(h00)),
                                                  __float2bfloat16(w01 - __bfloat162float(h01)));
        *(u32*)(smem8 + SO_W1L + off + 4) = hpair(__float2bfloat16(w08 - __bfloat162float(h08)),
                                                  __float2bfloat16(w09 - __bfloat162float(h09)));
    }
    {
        const float* Wg = isH ? W_hg : W_cg;
        for (int i = tid; i < 2048; i += NTHR) {      // W2: 64 frags x 32 lanes
            int fr = i >> 5, l = i & 31;
            int ktg = fr >> 1, ntw = fr & 1;
            int nl = ntw * 8 + (l >> 2);
            int pcol = (nl < 8) ? (n0_2 + nl) : (512 + n0_2 + (nl - 8));
            int k0 = ktg * 16 + 2 * (l & 3);
            float w00 = Wg[k0 * 1024 + pcol],       w01 = Wg[(k0 + 1) * 1024 + pcol];
            float w08 = Wg[(k0 + 8) * 1024 + pcol], w09 = Wg[(k0 + 9) * 1024 + pcol];
            __nv_bfloat16 h00 = __float2bfloat16(w00), h01 = __float2bfloat16(w01);
            __nv_bfloat16 h08 = __float2bfloat16(w08), h09 = __float2bfloat16(w09);
            u32 off = (u32)(fr * 256 + l * 8);
            *(u32*)(smem8 + SO_W2H + off)     = hpair(h00, h01);
            *(u32*)(smem8 + SO_W2H + off + 4) = hpair(h08, h09);
            *(u32*)(smem8 + SO_W2L + off)     = hpair(__float2bfloat16(w00 - __bfloat162float(h00)),
                                                      __float2bfloat16(w01 - __bfloat162float(h01)));
            *(u32*)(smem8 + SO_W2L + off + 4) = hpair(__float2bfloat16(w08 - __bfloat162float(h08)),
                                                      __float2bfloat16(w09 - __bfloat162float(h09)));
        }
    }
    if (tid < 16) {
        int gcol = (tid >> 2) * 512 + n0_1 + (tid & 3);
        sB1[tid] = b_ih[gcol] + b_hh[gcol];
    }
    // mbarriers: per (group, stage): full (count 32 = producer lanes via cp.async),
    //            empty (count 64 = 2 consumer warps x 32 lanes)
    if (tid == 0) {
        for (int g2 = 0; g2 < 24; ++g2) {
            mbar_init(sb + SO_MB + g2 * 16, 32);
            mbar_init(sb + SO_MB + g2 * 16 + 8, 64);
        }
    }

    // ---- t=0: z=0 -> mu=1e-6, std=ln2 ----
    if (tid < 256) {
        const float LN2 = 0.693147180559945309f;
        int i = cb * 256 + tid;       // b*512+n over grid
        int b = i >> 9, n = i & 511;
        float hs = fmaf(eps_h[i], LN2, 1e-6f);
        float cs = fmaf(eps_c[i], LN2, 1e-6f);
        __nv_bfloat16 hh = __float2bfloat16(hs);
        g_hh[i] = hh;
        g_hl[i] = __float2bfloat16(hs - __bfloat162float(hh));
        g_cs[i] = cs;
        size_t o = (size_t)b * 262656 + n;
        out[O_HMU  + o] = 1e-6f;
        out[O_HSTD + o] = LN2;
        out[O_CMU  + o] = 1e-6f;
        out[O_CSTD + o] = LN2;
    }
    grid_bar();

    const float* epsP = isH ? eps_h : eps_c;
    const size_t muB = isH ? O_HMU  : O_CMU;
    const size_t sdB = isH ? O_HSTD : O_CSTD;
    const size_t tB  = isH ? O_HT   : O_CT;
    const __nv_bfloat16* s2H = isH ? g_nhh : g_nch;
    const __nv_bfloat16* s2L = isH ? g_nhl : g_ncl;

    const int e_b  = tid & 63;        // stage-1 pointwise (tid<256)
    const int e_nn = (tid >> 6) & 3;
    const int e2_j = tid & 7;         // stage-2 epilogue (all 512)
    const int e2_b = tid >> 3;

    // pipeline cursors
    int fSlot = 0, fPh = 0;           // consumer (all warps)
    int eSlot = 0, ePh = 1;           // producer empty-wait (fresh-barrier convention)

    // ---- producer: wait empty, load slice, async-arrive full ----
    auto prodIssueSlot = [&](const char* srcH, const char* srcL) {
        u32 fullb = sb + SO_MB + (u32)(gid * 3 + eSlot) * 16;
        mbar_wait(fullb + 8, (u32)ePh);
        u32 dst = gBase + (u32)eSlot * 4608 + (u32)(lrow * 144 + half * 64);
        #pragma unroll
        for (int i = 0; i < 4; ++i) {
            cpa16(dst + i * 16,        srcH + i * 16);
            cpa16(dst + 2304 + i * 16, srcL + i * 16);
        }
        cpa_mbar_arrive(fullb);
        if (++eSlot == 3) { eSlot = 0; ePh ^= 1; }
    };
    auto prodIssue1 = [&](int s_, int c) {
        int grow = mt * 16 + lrow;
        if (c < 4) {
            size_t b0 = (((size_t)grow * Sn + s_) * 512) * 2 + (size_t)(c * 256 + kh * 128 + half * 64);
            prodIssueSlot((const char*)g_xh + b0, (const char*)g_xl + b0);
        } else {
            size_t b0 = (size_t)grow * 1024 + (size_t)((c - 4) * 256 + kh * 128 + half * 64);
            prodIssueSlot((const char*)g_hh + b0, (const char*)g_hl + b0);
        }
    };
    auto prodIssue2 = [&](int c) {
        size_t b0 = (size_t)(mt * 16 + lrow) * 1024 + (size_t)(c * 256 + kh * 128 + half * 64);
        prodIssueSlot((const char*)s2H + b0, (const char*)s2L + b0);
    };

    float acc[8];
    auto compute = [&](u32 wH, u32 wL, int ktgBase) {
        u32 fullb = sb + SO_MB + (u32)(gid * 3 + fSlot) * 16;
        mbar_wait(fullb, (u32)fPh);
        u32 ab = gBase + (u32)fSlot * 4608 + aOff;
        #pragma unroll
        for (int kt = 0; kt < 4; ++kt) {
            u32 ah[4], al[4];
            ldm4(ah, ab + kt * 32);
            ldm4(al, ab + kt * 32 + 2304);
            u32 wb = (u32)(((ktgBase + kt) * 2 + nt) * 256 + lane * 8);
            u32 ha, hb, la, lb;
            lds2(ha, hb, wH + wb);
            lds2(la, lb, wL + wb);
            float* A = acc + (kt & 1) * 4;
            mma16816(A, ah, ha, hb);
            mma16816(A, ah, la, lb);
            mma16816(A, al, ha, hb);
        }
        mbar_arrive(fullb + 8);       // empty
        if (++fSlot == 3) { fSlot = 0; fPh ^= 1; }
    };
    auto storeDp = [&]() {
        int rlo = mt * 16 + (lane >> 2);
        int cc  = nt * 8 + 2 * (lane & 3);
        float* dp = Dp + kh * 1152;
        dp[rlo * 18 + cc]           = acc[0] + acc[4];
        dp[rlo * 18 + cc + 1]       = acc[1] + acc[5];
        dp[(rlo + 8) * 18 + cc]     = acc[2] + acc[6];
        dp[(rlo + 8) * 18 + cc + 1] = acc[3] + acc[7];
    };

    // s=0 prologue: producers fill ring with x chunks 0,1,2
    if (producer) { prodIssue1(0, 0); prodIssue1(0, 1); prodIssue1(0, 2); }

    for (int s = 0; s < Sn; ++s) {
        // ================= stage 1 (8 chunks of K=128) =================
        #pragma unroll
        for (int i = 0; i < 8; ++i) acc[i] = 0.f;
        float cold_pre = 0.f;
        if (tid < 256) cold_pre = __ldcg(&g_cs[e_b * 512 + n0_1 + e_nn]);
        for (int c = 0; c < 8; ++c) {
            compute(sb + SO_W1H, sb + SO_W1L, c * 8 + kh * 4);
            if (producer && c <= 4) prodIssue1(s, c + 3);
        }
        storeDp();
        __syncthreads();
        if (tid < 256) {
            float gv[4];
            #pragma unroll
            for (int gg = 0; gg < 4; ++gg) {
                int c = gg * 4 + e_nn;
                gv[gg] = sB1[c] + Dp[e_b * 18 + c] + Dp[1152 + e_b * 18 + c];
            }
            int n = n0_1 + e_nn;
            float cv = sigm(gv[1]) * cold_pre + sigm(gv[0]) * tanhf(gv[2]);
            float hv = sigm(gv[3]) * tanhf(cv);
            __nv_bfloat16 ch = __float2bfloat16(cv);
            g_nch[e_b * 512 + n] = ch;
            g_ncl[e_b * 512 + n] = __float2bfloat16(cv - __bfloat162float(ch));
            __nv_bfloat16 hh2 = __float2bfloat16(hv);
            g_nhh[e_b * 512 + n] = hh2;
            g_nhl[e_b * 512 + n] = __float2bfloat16(hv - __bfloat162float(hh2));
        }
        grid_bar();

        // ================= stage 2 (4 chunks of K=128) =================
        if (producer) { prodIssue2(0); prodIssue2(1); prodIssue2(2); }
        #pragma unroll
        for (int i = 0; i < 8; ++i) acc[i] = 0.f;
        float eps_pre = __ldcg(&epsP[(size_t)(s + 1) * BH + (size_t)e2_b * 512 + n0_2 + e2_j]);
        for (int c = 0; c < 4; ++c) {
            compute(sb + SO_W2H, sb + SO_W2L, c * 8 + kh * 4);
            if (producer && c == 0) prodIssue2(3);
        }
        storeDp();
        __syncthreads();
        {   // sample epilogue: one (b, n) per thread
            int b = e2_b;
            float pm = Dp[b * 18 + e2_j]     + Dp[1152 + b * 18 + e2_j];
            float ps = Dp[b * 18 + 8 + e2_j] + Dp[1152 + b * 18 + 8 + e2_j];
            float mu = fminf(fmaxf(pm, 1e-6f), 1e6f);
            float sd = fmaxf(softplus(ps), 1e-6f);
            int n = n0_2 + e2_j;
            float smp = fmaf(eps_pre, sd, mu);
            size_t o = (size_t)b * 262656 + (size_t)(s + 1) * 512 + n;
            out[muB + o] = mu;
            out[sdB + o] = sd;
            if (isH) {
                out[O_HID + (size_t)b * 262144 + (size_t)s * 512 + n] = smp;
                __nv_bfloat16 hh2 = __float2bfloat16(smp);
                g_hh[b * 512 + n] = hh2;
                g_hl[b * 512 + n] = __float2bfloat16(smp - __bfloat162float(hh2));
            } else {
                g_cs[b * 512 + n] = smp;
            }
            if (s == Sn - 1) out[tB + (size_t)b * 512 + n] = smp;
        }
        // prefetch next step's x chunks across the grid barrier
        if (producer && s + 1 < Sn) {
            prodIssue1(s + 1, 0); prodIssue1(s + 1, 1); prodIssue1(s + 1, 2);
        }
        grid_bar();
    }
}

extern "C" void kernel_launch(void* const* d_in, const int* in_sizes, int n_in,
                              void* d_out, int out_size) {
    (void)in_sizes; (void)n_in; (void)out_size;
    const float* x    = (const float*)d_in[0];
    const float* W_ih = (const float*)d_in[1];
    const float* W_hh = (const float*)d_in[2];
    const float* b_ih = (const float*)d_in[3];
    const float* b_hh = (const float*)d_in[4];
    const float* W_hg = (const float*)d_in[5];
    const float* W_cg = (const float*)d_in[6];
    const float* eps_h = (const float*)d_in[7];
    const float* eps_c = (const float*)d_in[8];
    float* out = (float*)d_out;

    xsplit_kernel<<<65536, 256>>>(x);

    cudaFuncSetAttribute(rglstm, cudaFuncAttributeMaxDynamicSharedMemorySize, SMEM_BYTES);
    rglstm<<<NBLK, NTHR, SMEM_BYTES>>>(W_ih, W_hh, b_ih, b_hh,
                                       W_hg, W_cg, eps_h, eps_c, out);
}

// round 12
// speedup vs baseline: 1.2298x; 1.2298x over previous
#include <cuda_runtime.h>
#include <cuda_bf16.h>
#include <math.h>

#define NBLK 128
#define NTHR 512
#define Bn 64
#define Sn 512
#define BH 32768

typedef unsigned u32;
typedef unsigned long long u64;

// output section offsets (floats)
#define O_HID   0ull
#define O_HMU   16777216ull
#define O_HSTD  33587200ull
#define O_CMU   50397184ull
#define O_CSTD  67207168ull
#define O_HT    84017152ull
#define O_CT    84049920ull

// global state (bf16 hi/lo splits; [b][*] layouts)
__device__ __nv_bfloat16 g_xh[(size_t)Bn*Sn*512];   // [b][s][k]
__device__ __nv_bfloat16 g_xl[(size_t)Bn*Sn*512];
__device__ __nv_bfloat16 g_hh[BH], g_hl[BH];        // sampled h [b][n]
__device__ __nv_bfloat16 g_nhh[BH], g_nhl[BH];      // h_new
__device__ __nv_bfloat16 g_nch[BH], g_ncl[BH];      // c_new
__device__ float g_cs[BH];                          // sampled c (fp32)
__device__ unsigned g_cnt = 0;
__device__ volatile unsigned g_gen = 0;

__device__ __forceinline__ void grid_bar() {
    __syncthreads();
    if (threadIdx.x == 0) {
        __threadfence();
        unsigned gen = g_gen;
        if (atomicAdd(&g_cnt, 1u) == NBLK - 1) {
            g_cnt = 0;
            __threadfence();
            g_gen = gen + 1;
        } else {
            while (g_gen == gen) { }
            __threadfence();
        }
    }
    __syncthreads();
}

__device__ __forceinline__ float sigm(float v) { return 1.0f / (1.0f + expf(-v)); }
__device__ __forceinline__ float softplus(float v) {
    return fmaxf(v, 0.0f) + log1pf(expf(-fabsf(v)));
}

// ---------- PTX helpers (sm_80+, legal on compute_100) ----------
__device__ __forceinline__ u32 smem_u32(const void* p) {
    u32 a;
    asm("{ .reg .u64 t; cvta.to.shared.u64 t, %1; cvt.u32.u64 %0, t; }" : "=r"(a) : "l"(p));
    return a;
}
__device__ __forceinline__ void cpa16(u32 dst, const void* src) {
    asm volatile("cp.async.cg.shared.global [%0], [%1], 16;" :: "r"(dst), "l"(src));
}
__device__ __forceinline__ void cpa_commit() {
    asm volatile("cp.async.commit_group;" ::: "memory");
}
template <int N> __device__ __forceinline__ void cpa_wait() {
    asm volatile("cp.async.wait_group %0;" :: "n"(N) : "memory");
}
__device__ __forceinline__ void ldm4(u32* r, u32 addr) {
    asm volatile("ldmatrix.sync.aligned.m8n8.x4.shared.b16 {%0,%1,%2,%3}, [%4];"
                 : "=r"(r[0]), "=r"(r[1]), "=r"(r[2]), "=r"(r[3]) : "r"(addr));
}
__device__ __forceinline__ void lds2(u32& x, u32& y, u32 a) {
    asm volatile("ld.shared.v2.b32 {%0,%1}, [%2];" : "=r"(x), "=r"(y) : "r"(a));
}
__device__ __forceinline__ void mma16816(float* d, const u32* a, u32 b0, u32 b1) {
    asm volatile(
        "mma.sync.aligned.m16n8k16.row.col.f32.bf16.bf16.f32 "
        "{%0,%1,%2,%3}, {%4,%5,%6,%7}, {%8,%9}, {%0,%1,%2,%3};"
        : "+f"(d[0]), "+f"(d[1]), "+f"(d[2]), "+f"(d[3])
        : "r"(a[0]), "r"(a[1]), "r"(a[2]), "r"(a[3]), "r"(b0), "r"(b1));
}
__device__ __forceinline__ u32 hpair(__nv_bfloat16 a, __nv_bfloat16 b) {
    unsigned short ua = *(unsigned short*)&a, ub = *(unsigned short*)&b;
    return (u32)ua | ((u32)ub << 16);
}

// SMEM map (bytes)
// slot layout (per warp, 5 slots): 16 rows x 80B; row = [hi 32B][lo 32B][pad 16B]
#define SO_W1H  0
#define SO_W1L  32768
#define SO_W2H  65536
#define SO_W2L  81920
#define SO_A    98304
#define WRING   6400       // 5 slots x 1280
#define SLOT    1280
#define SO_DP   200704     // 4 x 64 x 18 f32 = 18432
#define SO_B1   219136
#define SMEM_BYTES 219200

// one-time x split
__global__ void xsplit_kernel(const float* __restrict__ x) {
    size_t i = (size_t)blockIdx.x * 256 + threadIdx.x;
    float v = x[i];
    __nv_bfloat16 hi = __float2bfloat16(v);
    g_xh[i] = hi;
    g_xl[i] = __float2bfloat16(v - __bfloat162float(hi));
}

__device__ __forceinline__ void waitAhead(int ahead) {
    if (ahead >= 4) cpa_wait<4>();
    else if (ahead == 3) cpa_wait<3>();
    else if (ahead == 2) cpa_wait<2>();
    else if (ahead == 1) cpa_wait<1>();
    else cpa_wait<0>();
}

__global__ __launch_bounds__(NTHR, 1)
void rglstm(const float* __restrict__ W_ih, const float* __restrict__ W_hh,
            const float* __restrict__ b_ih, const float* __restrict__ b_hh,
            const float* __restrict__ W_hg, const float* __restrict__ W_cg,
            const float* __restrict__ eps_h, const float* __restrict__ eps_c,
            float* __restrict__ out)
{
    extern __shared__ char smem8[];
    float* sB1 = (float*)(smem8 + SO_B1);
    float* Dp  = (float*)(smem8 + SO_DP);     // [4][64][18]

    const int tid  = threadIdx.x;
    const int wid  = tid >> 5;
    const int lane = tid & 31;
    const int cb   = blockIdx.x;
    const bool isH = cb < 64;
    const int n0_1 = cb << 2;
    const int n0_2 = (cb & 63) << 3;

    const u32 sb  = smem_u32(smem8);
    const u32 sbA = sb + SO_A;

    // warp roles: mt = m-tile (16 rows), kq = K-quarter; warp covers both n-halves
    const int mt = wid & 3;
    const int kq = wid >> 2;
    const bool xwarp = kq < 2;                 // stage-1 A slice is pure x
    const u32 gBase = sbA + (u32)wid * WRING;

    // loader lane geometry: lane -> (row, 16B half of the 32B hi/lo row segment)
    const int lrow = lane >> 1;
    const int half = lane & 1;
    const int row_b = mt * 16 + lrow;
    const u32 dOff = (u32)(lrow * 80 + half * 16);

    // ldmatrix per-lane offset (16 rows x 80B stride; lo at +32)
    const u32 aOff = (u32)((lane & 15) * 80 + ((lane >> 4) & 1) * 16);

    // ---- weight fragments (hi/lo), fragment-order SMEM (verified layout) ----
    for (int i = tid; i < 4096; i += NTHR) {          // W1: 128 frags x 32 lanes
        int fr = i >> 5, l = i & 31;
        int ktg = fr >> 1, ntw = fr & 1;
        int nl = ntw * 8 + (l >> 2);
        int gcol = (nl >> 2) * 512 + n0_1 + (nl & 3);
        int k0 = ktg * 16 + 2 * (l & 3);
        const float* base = (k0 < 512) ? (W_ih + gcol * 512) : (W_hh + gcol * 512 - 512);
        float w00 = base[k0], w01 = base[k0 + 1], w08 = base[k0 + 8], w09 = base[k0 + 9];
        __nv_bfloat16 h00 = __float2bfloat16(w00), h01 = __float2bfloat16(w01);
        __nv_bfloat16 h08 = __float2bfloat16(w08), h09 = __float2bfloat16(w09);
        u32 off = (u32)(fr * 256 + l * 8);
        *(u32*)(smem8 + SO_W1H + off)     = hpair(h00, h01);
        *(u32*)(smem8 + SO_W1H + off + 4) = hpair(h08, h09);
        *(u32*)(smem8 + SO_W1L + off)     = hpair(__float2bfloat16(w00 - __bfloat162float(h00)),
                                                  __float2bfloat16(w01 - __bfloat162float(h01)));
        *(u32*)(smem8 + SO_W1L + off + 4) = hpair(__float2bfloat16(w08 - __bfloat162float(h08)),
                                                  __float2bfloat16(w09 - __bfloat162float(h09)));
    }
    {
        const float* Wg = isH ? W_hg : W_cg;
        for (int i = tid; i < 2048; i += NTHR) {      // W2: 64 frags x 32 lanes
            int fr = i >> 5, l = i & 31;
            int ktg = fr >> 1, ntw = fr & 1;
            int nl = ntw * 8 + (l >> 2);
            int pcol = (nl < 8) ? (n0_2 + nl) : (512 + n0_2 + (nl - 8));
            int k0 = ktg * 16 + 2 * (l & 3);
            float w00 = Wg[k0 * 1024 + pcol],       w01 = Wg[(k0 + 1) * 1024 + pcol];
            float w08 = Wg[(k0 + 8) * 1024 + pcol], w09 = Wg[(k0 + 9) * 1024 + pcol];
            __nv_bfloat16 h00 = __float2bfloat16(w00), h01 = __float2bfloat16(w01);
            __nv_bfloat16 h08 = __float2bfloat16(w08), h09 = __float2bfloat16(w09);
            u32 off = (u32)(fr * 256 + l * 8);
            *(u32*)(smem8 + SO_W2H + off)     = hpair(h00, h01);
            *(u32*)(smem8 + SO_W2H + off + 4) = hpair(h08, h09);
            *(u32*)(smem8 + SO_W2L + off)     = hpair(__float2bfloat16(w00 - __bfloat162float(h00)),
                                                      __float2bfloat16(w01 - __bfloat162float(h01)));
            *(u32*)(smem8 + SO_W2L + off + 4) = hpair(__float2bfloat16(w08 - __bfloat162float(h08)),
                                                      __float2bfloat16(w09 - __bfloat162float(h09)));
        }
    }
    if (tid < 16) {
        int gcol = (tid >> 2) * 512 + n0_1 + (tid & 3);
        sB1[tid] = b_ih[gcol] + b_hh[gcol];
    }

    // ---- t=0: z=0 -> mu=1e-6, std=ln2 ----
    if (tid < 256) {
        const float LN2 = 0.693147180559945309f;
        int i = cb * 256 + tid;       // b*512+n over grid
        int b = i >> 9, n = i & 511;
        float hs = fmaf(eps_h[i], LN2, 1e-6f);
        float cs = fmaf(eps_c[i], LN2, 1e-6f);
        __nv_bfloat16 hh = __float2bfloat16(hs);
        g_hh[i] = hh;
        g_hl[i] = __float2bfloat16(hs - __bfloat162float(hh));
        g_cs[i] = cs;
        size_t o = (size_t)b * 262656 + n;
        out[O_HMU  + o] = 1e-6f;
        out[O_HSTD + o] = LN2;
        out[O_CMU  + o] = 1e-6f;
        out[O_CSTD + o] = LN2;
    }
    grid_bar();

    const float* epsP = isH ? eps_h : eps_c;
    const size_t muB = isH ? O_HMU  : O_CMU;
    const size_t sdB = isH ? O_HSTD : O_CSTD;
    const size_t tB  = isH ? O_HT   : O_CT;
    const __nv_bfloat16* s2H = isH ? g_nhh : g_nch;
    const __nv_bfloat16* s2L = isH ? g_nhl : g_ncl;

    const int e_b  = tid & 63;        // stage-1 pointwise (tid<256)
    const int e_nn = (tid >> 6) & 3;
    const int e2_j = tid & 7;         // stage-2 epilogue (all 512)
    const int e2_b = tid >> 3;

    // ---- per-warp loaders: 1 commit group per 16-k sub-chunk ----
    auto issueSlot = [&](int slot, const char* srcH, const char* srcL) {
        u32 d = gBase + (u32)slot * SLOT + dOff;
        cpa16(d,      srcH);
        cpa16(d + 32, srcL);
        cpa_commit();
    };
    auto issue1 = [&](int s_, int c) {
        int slot = c % 5;
        if (xwarp) {
            size_t off = ((((size_t)row_b * Sn + s_) * 512) + (size_t)(kq * 256 + c * 16 + half * 8)) * 2;
            issueSlot(slot, (const char*)g_xh + off, (const char*)g_xl + off);
        } else {
            size_t off = ((size_t)row_b * 512 + (size_t)((kq - 2) * 256 + c * 16 + half * 8)) * 2;
            issueSlot(slot, (const char*)g_hh + off, (const char*)g_hl + off);
        }
    };
    auto issue2 = [&](int c) {
        int slot = c % 5;
        size_t off = ((size_t)row_b * 512 + (size_t)(kq * 128 + c * 16 + half * 8)) * 2;
        issueSlot(slot, (const char*)s2H + off, (const char*)s2L + off);
    };

    float acc[16];                    // [k-parity][n-half][4]
    auto compute = [&](int c, u32 wH, u32 wL, int ktg) {
        u32 ab = gBase + (u32)(c % 5) * SLOT + aOff;
        u32 ah4[4], al4[4];
        ldm4(ah4, ab);
        ldm4(al4, ab + 32);
        u32 wb = (u32)(ktg * 512 + lane * 8);
        u32 h0a, h0b, h1a, h1b, l0a, l0b, l1a, l1b;
        lds2(h0a, h0b, wH + wb);
        lds2(h1a, h1b, wH + wb + 256);
        lds2(l0a, l0b, wL + wb);
        lds2(l1a, l1b, wL + wb + 256);
        float* A0 = acc + (c & 1) * 8;
        float* A1 = A0 + 4;
        mma16816(A0, ah4, h0a, h0b);
        mma16816(A1, ah4, h1a, h1b);
        mma16816(A0, ah4, l0a, l0b);
        mma16816(A1, ah4, l1a, l1b);
        mma16816(A0, al4, h0a, h0b);
        mma16816(A1, al4, h1a, h1b);
    };
    auto storeDp = [&]() {
        int rlo = mt * 16 + (lane >> 2);
        int cc  = 2 * (lane & 3);
        float* dp = Dp + kq * 1152;
        #pragma unroll
        for (int nt = 0; nt < 2; ++nt) {
            float* A = acc + nt * 4;
            int c = nt * 8 + cc;
            dp[rlo * 18 + c]           = A[0] + A[8];
            dp[rlo * 18 + c + 1]       = A[1] + A[9];
            dp[(rlo + 8) * 18 + c]     = A[2] + A[10];
            dp[(rlo + 8) * 18 + c + 1] = A[3] + A[11];
        }
    };

    // s=0 prologue: x-warps pre-fill ring
    if (xwarp) {
        #pragma unroll
        for (int p = 0; p < 5; ++p) issue1(0, p);
    }

    for (int s = 0; s < Sn; ++s) {
        // ================= stage 1: 16 sub-chunks of 16 k per warp =================
        if (!xwarp) {
            #pragma unroll
            for (int p = 0; p < 5; ++p) issue1(s, p);
        }
        float cold_pre = 0.f;
        if (tid < 256) cold_pre = __ldcg(&g_cs[e_b * 512 + n0_1 + e_nn]);
        #pragma unroll
        for (int i = 0; i < 16; ++i) acc[i] = 0.f;
        #pragma unroll
        for (int c = 0; c < 16; ++c) {
            int ahead = 16 - 1 - c; if (ahead > 4) ahead = 4;
            waitAhead(ahead);
            __syncwarp();
            compute(c, sb + SO_W1H, sb + SO_W1L, kq * 16 + c);
            __syncwarp();
            if (c + 5 < 16) issue1(s, c + 5);
        }
        storeDp();
        __syncthreads();
        if (tid < 256) {
            float gv[4];
            #pragma unroll
            for (int gg = 0; gg < 4; ++gg) {
                int c = gg * 4 + e_nn;
                float v = sB1[c];
                #pragma unroll
                for (int kp = 0; kp < 4; ++kp) v += Dp[kp * 1152 + e_b * 18 + c];
                gv[gg] = v;
            }
            int n = n0_1 + e_nn;
            float cv = sigm(gv[1]) * cold_pre + sigm(gv[0]) * tanhf(gv[2]);
            float hv = sigm(gv[3]) * tanhf(cv);
            __nv_bfloat16 ch = __float2bfloat16(cv);
            g_nch[e_b * 512 + n] = ch;
            g_ncl[e_b * 512 + n] = __float2bfloat16(cv - __bfloat162float(ch));
            __nv_bfloat16 hh2 = __float2bfloat16(hv);
            g_nhh[e_b * 512 + n] = hh2;
            g_nhl[e_b * 512 + n] = __float2bfloat16(hv - __bfloat162float(hh2));
        }
        grid_bar();

        // ================= stage 2: 8 sub-chunks of 16 k per warp =================
        #pragma unroll
        for (int p = 0; p < 5; ++p) issue2(p);
        float eps_pre = __ldcg(&epsP[(size_t)(s + 1) * BH + (size_t)e2_b * 512 + n0_2 + e2_j]);
        #pragma unroll
        for (int i = 0; i < 16; ++i) acc[i] = 0.f;
        #pragma unroll
        for (int c = 0; c < 8; ++c) {
            int ahead = 8 - 1 - c; if (ahead > 4) ahead = 4;
            waitAhead(ahead);
            __syncwarp();
            compute(c, sb + SO_W2H, sb + SO_W2L, kq * 8 + c);
            __syncwarp();
            if (c + 5 < 8) issue2(c + 5);
        }
        storeDp();
        __syncthreads();
        {   // sample epilogue: one (b, n) per thread
            int b = e2_b;
            float pm = 0.f, ps = 0.f;
            #pragma unroll
            for (int kp = 0; kp < 4; ++kp) {
                pm += Dp[kp * 1152 + b * 18 + e2_j];
                ps += Dp[kp * 1152 + b * 18 + 8 + e2_j];
            }
            float mu = fminf(fmaxf(pm, 1e-6f), 1e6f);
            float sd = fmaxf(softplus(ps), 1e-6f);
            int n = n0_2 + e2_j;
            float smp = fmaf(eps_pre, sd, mu);
            size_t o = (size_t)b * 262656 + (size_t)(s + 1) * 512 + n;
            out[muB + o] = mu;
            out[sdB + o] = sd;
            if (isH) {
                out[O_HID + (size_t)b * 262144 + (size_t)s * 512 + n] = smp;
                __nv_bfloat16 hh2 = __float2bfloat16(smp);
                g_hh[b * 512 + n] = hh2;
                g_hl[b * 512 + n] = __float2bfloat16(smp - __bfloat162float(hh2));
            } else {
                g_cs[b * 512 + n] = smp;
            }
            if (s == Sn - 1) out[tB + (size_t)b * 512 + n] = smp;
        }
        // x-warps prefetch next step's stage-1 sub-chunks across the barrier
        if (xwarp && s + 1 < Sn) {
            #pragma unroll
            for (int p = 0; p < 5; ++p) issue1(s + 1, p);
        }
        grid_bar();
    }
}

extern "C" void kernel_launch(void* const* d_in, const int* in_sizes, int n_in,
                              void* d_out, int out_size) {
    (void)in_sizes; (void)n_in; (void)out_size;
    const float* x    = (const float*)d_in[0];
    const float* W_ih = (const float*)d_in[1];
    const float* W_hh = (const float*)d_in[2];
    const float* b_ih = (const float*)d_in[3];
    const float* b_hh = (const float*)d_in[4];
    const float* W_hg = (const float*)d_in[5];
    const float* W_cg = (const float*)d_in[6];
    const float* eps_h = (const float*)d_in[7];
    const float* eps_c = (const float*)d_in[8];
    float* out = (float*)d_out;

    xsplit_kernel<<<65536, 256>>>(x);

    cudaFuncSetAttribute(rglstm, cudaFuncAttributeMaxDynamicSharedMemorySize, SMEM_BYTES);
    rglstm<<<NBLK, NTHR, SMEM_BYTES>>>(W_ih, W_hh, b_ih, b_hh,
                                       W_hg, W_cg, eps_h, eps_c, out);
}

// round 13
// speedup vs baseline: 1.2775x; 1.0388x over previous
#include <cuda_runtime.h>
#include <cuda_bf16.h>
#include <math.h>

#define NBLK 128
#define NTHR 512
#define Bn 64
#define Sn 512
#define BH 32768

typedef unsigned u32;
typedef unsigned long long u64;

// output section offsets (floats)
#define O_HID   0ull
#define O_HMU   16777216ull
#define O_HSTD  33587200ull
#define O_CMU   50397184ull
#define O_CSTD  67207168ull
#define O_HT    84017152ull
#define O_CT    84049920ull

// global state (bf16 hi/lo splits; [b][*] layouts)
__device__ __nv_bfloat16 g_xh[(size_t)Bn*Sn*512];   // [b][s][k]
__device__ __nv_bfloat16 g_xl[(size_t)Bn*Sn*512];
__device__ __nv_bfloat16 g_hh[BH], g_hl[BH];        // sampled h [b][n]
__device__ __nv_bfloat16 g_nhh[BH], g_nhl[BH];      // h_new
__device__ __nv_bfloat16 g_nch[BH], g_ncl[BH];      // c_new
__device__ float g_cs[BH];                          // sampled c (fp32)
__device__ float g_x1[(size_t)Sn*128*1024];         // precomputed x-gates [s][cb][c][b]
__device__ int g_flag[128*32];
__device__ int g_rel;

// flag-array grid barrier (no same-address atomic chain)
__device__ __forceinline__ void grid_bar(int& gen) {
    __syncthreads();
    ++gen;
    if (threadIdx.x == 0) {
        __threadfence();
        *(volatile int*)&g_flag[blockIdx.x * 32] = gen;
    }
    if (blockIdx.x == 0) {
        if (threadIdx.x < 128)
            while (*(volatile int*)&g_flag[threadIdx.x * 32] < gen) { }
        __syncthreads();
        if (threadIdx.x == 0) { __threadfence(); *(volatile int*)&g_rel = gen; }
    }
    if (threadIdx.x == 0) {
        while (*(volatile int*)&g_rel < gen) { }
        __threadfence();
    }
    __syncthreads();
}

__device__ __forceinline__ float sigm(float v) { return 1.0f / (1.0f + expf(-v)); }
__device__ __forceinline__ float softplus(float v) {
    return fmaxf(v, 0.0f) + log1pf(expf(-fabsf(v)));
}

// ---------- PTX helpers (sm_80+, legal on compute_100) ----------
__device__ __forceinline__ u32 smem_u32(const void* p) {
    u32 a;
    asm("{ .reg .u64 t; cvta.to.shared.u64 t, %1; cvt.u32.u64 %0, t; }" : "=r"(a) : "l"(p));
    return a;
}
__device__ __forceinline__ void cpa16(u32 dst, const void* src) {
    asm volatile("cp.async.cg.shared.global [%0], [%1], 16;" :: "r"(dst), "l"(src));
}
__device__ __forceinline__ void cpa_commit() {
    asm volatile("cp.async.commit_group;" ::: "memory");
}
template <int N> __device__ __forceinline__ void cpa_wait() {
    asm volatile("cp.async.wait_group %0;" :: "n"(N) : "memory");
}
__device__ __forceinline__ void ldm4(u32* r, u32 addr) {
    asm volatile("ldmatrix.sync.aligned.m8n8.x4.shared.b16 {%0,%1,%2,%3}, [%4];"
                 : "=r"(r[0]), "=r"(r[1]), "=r"(r[2]), "=r"(r[3]) : "r"(addr));
}
__device__ __forceinline__ void lds2(u32& x, u32& y, u32 a) {
    asm volatile("ld.shared.v2.b32 {%0,%1}, [%2];" : "=r"(x), "=r"(y) : "r"(a));
}
__device__ __forceinline__ void mma16816(float* d, const u32* a, u32 b0, u32 b1) {
    asm volatile(
        "mma.sync.aligned.m16n8k16.row.col.f32.bf16.bf16.f32 "
        "{%0,%1,%2,%3}, {%4,%5,%6,%7}, {%8,%9}, {%0,%1,%2,%3};"
        : "+f"(d[0]), "+f"(d[1]), "+f"(d[2]), "+f"(d[3])
        : "r"(a[0]), "r"(a[1]), "r"(a[2]), "r"(a[3]), "r"(b0), "r"(b1));
}
__device__ __forceinline__ u32 hpair(__nv_bfloat16 a, __nv_bfloat16 b) {
    unsigned short ua = *(unsigned short*)&a, ub = *(unsigned short*)&b;
    return (u32)ua | ((u32)ub << 16);
}

#define ABUF 34816      // per buffer: hi [64][272B] + lo at +17408
#define AST  272

// main-kernel SMEM map (bytes)
#define SO_W1H  0
#define SO_W1L  16384
#define SO_W2H  32768
#define SO_W2L  49152
#define SO_A    65536      // 3 x 34816
#define SO_DP   169984     // 4 x 64 x 18 f32
#define SO_B1   188416
#define SMEM_BYTES 188480

// precomp-kernel SMEM map
#define SP_WXH  0
#define SP_WXL  16384
#define SP_A    32768      // 3 x 34816
#define SP_DP   137216
#define SMEM_P  155648

// one-time x split
__global__ void xsplit_kernel(const float* __restrict__ x) {
    size_t i = (size_t)blockIdx.x * 256 + threadIdx.x;
    float v = x[i];
    __nv_bfloat16 hi = __float2bfloat16(v);
    g_xh[i] = hi;
    g_xl[i] = __float2bfloat16(v - __bfloat162float(hi));
}

// ---------------- precompute: X1[s][cb] = x_s @ W_ih^T (16 cols per cb) ----------------
__global__ __launch_bounds__(512, 1)
void precomp(const float* __restrict__ W_ih) {
    extern __shared__ char smem8[];
    float* Dp = (float*)(smem8 + SP_DP);

    const int tid  = threadIdx.x;
    const int wid  = tid >> 5;
    const int lane = tid & 31;
    const int cb   = blockIdx.x;
    const int sblk = blockIdx.y;
    const int n0_1 = cb << 2;

    const u32 sb  = smem_u32(smem8);
    const u32 sbA = sb + SP_A;

    const int mt    = wid & 3;
    const int khalf = wid >> 2;           // 0..3
    const u32 aRow  = (u32)((mt * 16 + (lane & 7) + ((lane >> 3) & 1) * 8) * AST);
    const u32 aColH = (u32)(((lane >> 4) & 1) * 16);
    const int lrow  = tid >> 3;
    const u32 lq32  = (u32)((tid & 7) << 5);

    // W fragments (x-part, hi/lo)
    for (int i = tid; i < 2048; i += 512) {
        int fr = i >> 5, l = i & 31;
        int ktg = fr >> 1, ntw = fr & 1;
        int nl = ntw * 8 + (l >> 2);
        int gcol = (nl >> 2) * 512 + n0_1 + (nl & 3);
        int k0 = ktg * 16 + 2 * (l & 3);
        const float* base = W_ih + gcol * 512;
        float w00 = base[k0], w01 = base[k0 + 1], w08 = base[k0 + 8], w09 = base[k0 + 9];
        __nv_bfloat16 h00 = __float2bfloat16(w00), h01 = __float2bfloat16(w01);
        __nv_bfloat16 h08 = __float2bfloat16(w08), h09 = __float2bfloat16(w09);
        u32 off = (u32)(fr * 256 + l * 8);
        *(u32*)(smem8 + SP_WXH + off)     = hpair(h00, h01);
        *(u32*)(smem8 + SP_WXH + off + 4) = hpair(h08, h09);
        *(u32*)(smem8 + SP_WXL + off)     = hpair(__float2bfloat16(w00 - __bfloat162float(h00)),
                                                  __float2bfloat16(w01 - __bfloat162float(h01)));
        *(u32*)(smem8 + SP_WXL + off + 4) = hpair(__float2bfloat16(w08 - __bfloat162float(h08)),
                                                  __float2bfloat16(w09 - __bfloat162float(h09)));
    }
    __syncthreads();

    auto issueP = [&](int gc) {
        int s_ = sblk * 64 + (gc >> 2);
        int c_ = gc & 3;
        size_t o = ((size_t)lrow * Sn + s_) * 512 + (size_t)c_ * 128;
        u32 d = sbA + (u32)((gc % 3) * ABUF) + (u32)(lrow * AST) + lq32;
        const char* gh = (const char*)(g_xh + o) + lq32;
        const char* gl = (const char*)(g_xl + o) + lq32;
        cpa16(d,              gh);
        cpa16(d + 16,         gh + 16);
        cpa16(d + 17408,      gl);
        cpa16(d + 17408 + 16, gl + 16);
        cpa_commit();
    };

    float acc[16];
    auto compute = [&](int bf, u32 wH, u32 wL, int ktgBase) {
        u32 ab = sbA + (u32)(bf * ABUF) + aRow + aColH + (u32)(khalf * 64);
        #pragma unroll
        for (int kt = 0; kt < 2; ++kt) {
            u32 ah[4], al[4];
            ldm4(ah, ab + kt * 32);
            ldm4(al, ab + kt * 32 + 17408);
            u32 wb = (u32)((ktgBase + kt) * 512 + lane * 8);
            u32 h0a, h0b, h1a, h1b, l0a, l0b, l1a, l1b;
            lds2(h0a, h0b, wH + wb);
            lds2(h1a, h1b, wH + wb + 256);
            lds2(l0a, l0b, wL + wb);
            lds2(l1a, l1b, wL + wb + 256);
            float* A0 = acc + kt * 8;
            float* A1 = A0 + 4;
            mma16816(A0, ah, h0a, h0b);
            mma16816(A1, ah, h1a, h1b);
            mma16816(A0, ah, l0a, l0b);
            mma16816(A1, ah, l1a, l1b);
            mma16816(A0, al, h0a, h0b);
            mma16816(A1, al, h1a, h1b);
        }
    };
    auto storeDp = [&]() {
        int rlo = mt * 16 + (lane >> 2);
        int cc  = 2 * (lane & 3);
        float* dp = Dp + khalf * 1152;
        #pragma unroll
        for (int nt = 0; nt < 2; ++nt) {
            float* A = acc + nt * 4;
            int c = nt * 8 + cc;
            dp[rlo * 18 + c]           = A[0] + A[8];
            dp[rlo * 18 + c + 1]       = A[1] + A[9];
            dp[(rlo + 8) * 18 + c]     = A[2] + A[10];
            dp[(rlo + 8) * 18 + c + 1] = A[3] + A[11];
        }
    };

    const int e_b  = tid & 63;
    const int e_nn = (tid >> 6) & 3;

    issueP(0); issueP(1);
    for (int sl = 0; sl < 64; ++sl) {
        #pragma unroll
        for (int i = 0; i < 16; ++i) acc[i] = 0.f;
        #pragma unroll
        for (int c = 0; c < 4; ++c) {
            int gc = sl * 4 + c;
            if (gc == 255) cpa_wait<0>(); else cpa_wait<1>();
            __syncthreads();
            compute(gc % 3, sb + SP_WXH, sb + SP_WXL, c * 8 + khalf * 2);
            if (gc + 2 < 256) issueP(gc + 2);
        }
        storeDp();
        __syncthreads();
        if (tid < 256) {
            int s_ = sblk * 64 + sl;
            float* dst = g_x1 + ((size_t)s_ * 128 + cb) * 1024;
            #pragma unroll
            for (int gg = 0; gg < 4; ++gg) {
                int c2 = gg * 4 + e_nn;
                float v = 0.f;
                #pragma unroll
                for (int kp = 0; kp < 4; ++kp) v += Dp[kp * 1152 + e_b * 18 + c2];
                dst[c2 * 64 + e_b] = v;
            }
        }
    }
}

// ---------------- main persistent kernel ----------------
__global__ __launch_bounds__(NTHR, 1)
void rglstm(const float* __restrict__ W_ih, const float* __restrict__ W_hh,
            const float* __restrict__ b_ih, const float* __restrict__ b_hh,
            const float* __restrict__ W_hg, const float* __restrict__ W_cg,
            const float* __restrict__ eps_h, const float* __restrict__ eps_c,
            float* __restrict__ out)
{
    extern __shared__ char smem8[];
    float* sB1 = (float*)(smem8 + SO_B1);
    float* Dp  = (float*)(smem8 + SO_DP);     // [4][64][18]

    const int tid  = threadIdx.x;
    const int wid  = tid >> 5;
    const int lane = tid & 31;
    const int cb   = blockIdx.x;
    const bool isH = cb < 64;
    const int n0_1 = cb << 2;
    const int n0_2 = (cb & 63) << 3;

    const u32 sb  = smem_u32(smem8);
    const u32 sbA = sb + SO_A;

    const int mt    = wid & 3;
    const int khalf = wid >> 2;               // 0..3
    const u32 aRow  = (u32)((mt * 16 + (lane & 7) + ((lane >> 3) & 1) * 8) * AST);
    const u32 aColH = (u32)(((lane >> 4) & 1) * 16);
    const int lrow  = tid >> 3;
    const u32 lq32  = (u32)((tid & 7) << 5);

    // ---- W1 fragments (h-part only, K=512), hi/lo ----
    for (int i = tid; i < 2048; i += NTHR) {
        int fr = i >> 5, l = i & 31;
        int ktg = fr >> 1, ntw = fr & 1;
        int nl = ntw * 8 + (l >> 2);
        int gcol = (nl >> 2) * 512 + n0_1 + (nl & 3);
        int k0 = ktg * 16 + 2 * (l & 3);
        const float* base = W_hh + gcol * 512;
        float w00 = base[k0], w01 = base[k0 + 1], w08 = base[k0 + 8], w09 = base[k0 + 9];
        __nv_bfloat16 h00 = __float2bfloat16(w00), h01 = __float2bfloat16(w01);
        __nv_bfloat16 h08 = __float2bfloat16(w08), h09 = __float2bfloat16(w09);
        u32 off = (u32)(fr * 256 + l * 8);
        *(u32*)(smem8 + SO_W1H + off)     = hpair(h00, h01);
        *(u32*)(smem8 + SO_W1H + off + 4) = hpair(h08, h09);
        *(u32*)(smem8 + SO_W1L + off)     = hpair(__float2bfloat16(w00 - __bfloat162float(h00)),
                                                  __float2bfloat16(w01 - __bfloat162float(h01)));
        *(u32*)(smem8 + SO_W1L + off + 4) = hpair(__float2bfloat16(w08 - __bfloat162float(h08)),
                                                  __float2bfloat16(w09 - __bfloat162float(h09)));
    }
    {   // W2 fragments
        const float* Wg = isH ? W_hg : W_cg;
        for (int i = tid; i < 2048; i += NTHR) {
            int fr = i >> 5, l = i & 31;
            int ktg = fr >> 1, ntw = fr & 1;
            int nl = ntw * 8 + (l >> 2);
            int pcol = (nl < 8) ? (n0_2 + nl) : (512 + n0_2 + (nl - 8));
            int k0 = ktg * 16 + 2 * (l & 3);
            float w00 = Wg[k0 * 1024 + pcol],       w01 = Wg[(k0 + 1) * 1024 + pcol];
            float w08 = Wg[(k0 + 8) * 1024 + pcol], w09 = Wg[(k0 + 9) * 1024 + pcol];
            __nv_bfloat16 h00 = __float2bfloat16(w00), h01 = __float2bfloat16(w01);
            __nv_bfloat16 h08 = __float2bfloat16(w08), h09 = __float2bfloat16(w09);
            u32 off = (u32)(fr * 256 + l * 8);
            *(u32*)(smem8 + SO_W2H + off)     = hpair(h00, h01);
            *(u32*)(smem8 + SO_W2H + off + 4) = hpair(h08, h09);
            *(u32*)(smem8 + SO_W2L + off)     = hpair(__float2bfloat16(w00 - __bfloat162float(h00)),
                                                      __float2bfloat16(w01 - __bfloat162float(h01)));
            *(u32*)(smem8 + SO_W2L + off + 4) = hpair(__float2bfloat16(w08 - __bfloat162float(h08)),
                                                      __float2bfloat16(w09 - __bfloat162float(h09)));
        }
    }
    if (tid < 16) {
        int gcol = (tid >> 2) * 512 + n0_1 + (tid & 3);
        sB1[tid] = b_ih[gcol] + b_hh[gcol];
    }

    // ---- t=0: z=0 -> mu=1e-6, std=ln2 ----
    if (tid < 256) {
        const float LN2 = 0.693147180559945309f;
        int i = cb * 256 + tid;       // b*512+n over grid
        int b = i >> 9, n = i & 511;
        float hs = fmaf(eps_h[i], LN2, 1e-6f);
        float cs = fmaf(eps_c[i], LN2, 1e-6f);
        __nv_bfloat16 hh = __float2bfloat16(hs);
        g_hh[i] = hh;
        g_hl[i] = __float2bfloat16(hs - __bfloat162float(hh));
        g_cs[i] = cs;
        size_t o = (size_t)b * 262656 + n;
        out[O_HMU  + o] = 1e-6f;
        out[O_HSTD + o] = LN2;
        out[O_CMU  + o] = 1e-6f;
        out[O_CSTD + o] = LN2;
    }
    int gen = 0;
    grid_bar(gen);

    const float* epsP = isH ? eps_h : eps_c;
    const size_t muB = isH ? O_HMU  : O_CMU;
    const size_t sdB = isH ? O_HSTD : O_CSTD;
    const size_t tB  = isH ? O_HT   : O_CT;
    const __nv_bfloat16* s2H = isH ? g_nhh : g_nch;
    const __nv_bfloat16* s2L = isH ? g_nhl : g_ncl;

    const int e_b  = tid & 63;
    const int e_nn = (tid >> 6) & 3;
    const int e2_j = tid & 7;
    const int e2_b = tid >> 3;

    auto issueHL = [&](const __nv_bfloat16* H, const __nv_bfloat16* L, int bf) {
        u32 d = sbA + (u32)(bf * ABUF) + (u32)(lrow * AST) + lq32;
        const char* gh = (const char*)H + lq32;
        const char* gl = (const char*)L + lq32;
        cpa16(d,              gh);
        cpa16(d + 16,         gh + 16);
        cpa16(d + 17408,      gl);
        cpa16(d + 17408 + 16, gl + 16);
        cpa_commit();
    };
    auto issue1 = [&](int c, int bf) {
        size_t o = (size_t)lrow * 512 + (size_t)c * 128;
        issueHL(g_hh + o, g_hl + o, bf);
    };
    auto issue2 = [&](int c, int bf) {
        size_t o = (size_t)lrow * 512 + (size_t)c * 128;
        issueHL(s2H + o, s2L + o, bf);
    };

    float acc[16];
    auto compute = [&](int bf, u32 wH, u32 wL, int ktgBase) {
        u32 ab = sbA + (u32)(bf * ABUF) + aRow + aColH + (u32)(khalf * 64);
        #pragma unroll
        for (int kt = 0; kt < 2; ++kt) {
            u32 ah[4], al[4];
            ldm4(ah, ab + kt * 32);
            ldm4(al, ab + kt * 32 + 17408);
            u32 wb = (u32)((ktgBase + kt) * 512 + lane * 8);
            u32 h0a, h0b, h1a, h1b, l0a, l0b, l1a, l1b;
            lds2(h0a, h0b, wH + wb);
            lds2(h1a, h1b, wH + wb + 256);
            lds2(l0a, l0b, wL + wb);
            lds2(l1a, l1b, wL + wb + 256);
            float* A0 = acc + kt * 8;
            float* A1 = A0 + 4;
            mma16816(A0, ah, h0a, h0b);
            mma16816(A1, ah, h1a, h1b);
            mma16816(A0, ah, l0a, l0b);
            mma16816(A1, ah, l1a, l1b);
            mma16816(A0, al, h0a, h0b);
            mma16816(A1, al, h1a, h1b);
        }
    };
    auto storeDp = [&]() {
        int rlo = mt * 16 + (lane >> 2);
        int cc  = 2 * (lane & 3);
        float* dp = Dp + khalf * 1152;
        #pragma unroll
        for (int nt = 0; nt < 2; ++nt) {
            float* A = acc + nt * 4;
            int c = nt * 8 + cc;
            dp[rlo * 18 + c]           = A[0] + A[8];
            dp[rlo * 18 + c + 1]       = A[1] + A[9];
            dp[(rlo + 8) * 18 + c]     = A[2] + A[10];
            dp[(rlo + 8) * 18 + c + 1] = A[3] + A[11];
        }
    };

    for (int s = 0; s < Sn; ++s) {
        // ================= stage 1 (h-GEMM, 4 chunks of K=128) =================
        #pragma unroll
        for (int i = 0; i < 16; ++i) acc[i] = 0.f;
        issue1(0, 0);
        issue1(1, 1);
        float x1r[4] = {0.f, 0.f, 0.f, 0.f};
        float cold_pre = 0.f;
        if (tid < 256) {
            cold_pre = __ldcg(&g_cs[e_b * 512 + n0_1 + e_nn]);
            const float* xp = g_x1 + ((size_t)s * 128 + cb) * 1024 + e_nn * 64 + e_b;
            x1r[0] = __ldcg(xp);
            x1r[1] = __ldcg(xp + 256);
            x1r[2] = __ldcg(xp + 512);
            x1r[3] = __ldcg(xp + 768);
        }
        #pragma unroll
        for (int c = 0; c < 4; ++c) {
            if (c < 3) cpa_wait<1>(); else cpa_wait<0>();
            __syncthreads();
            compute(c % 3, sb + SO_W1H, sb + SO_W1L, c * 8 + khalf * 2);
            if (c + 2 < 4) issue1(c + 2, (c + 2) % 3);
        }
        storeDp();
        __syncthreads();
        if (tid < 256) {
            float gv[4];
            #pragma unroll
            for (int gg = 0; gg < 4; ++gg) {
                int c = gg * 4 + e_nn;
                float v = sB1[c] + x1r[gg];
                #pragma unroll
                for (int kp = 0; kp < 4; ++kp) v += Dp[kp * 1152 + e_b * 18 + c];
                gv[gg] = v;
            }
            int n = n0_1 + e_nn;
            float cv = sigm(gv[1]) * cold_pre + sigm(gv[0]) * tanhf(gv[2]);
            float hv = sigm(gv[3]) * tanhf(cv);
            __nv_bfloat16 ch = __float2bfloat16(cv);
            g_nch[e_b * 512 + n] = ch;
            g_ncl[e_b * 512 + n] = __float2bfloat16(cv - __bfloat162float(ch));
            __nv_bfloat16 hh2 = __float2bfloat16(hv);
            g_nhh[e_b * 512 + n] = hh2;
            g_nhl[e_b * 512 + n] = __float2bfloat16(hv - __bfloat162float(hh2));
        }
        grid_bar(gen);

        // ================= stage 2 (sample GEMM, 4 chunks of K=128) =================
        #pragma unroll
        for (int i = 0; i < 16; ++i) acc[i] = 0.f;
        issue2(0, 0);
        issue2(1, 1);
        float eps_pre = __ldcg(&epsP[(size_t)(s + 1) * BH + (size_t)e2_b * 512 + n0_2 + e2_j]);
        #pragma unroll
        for (int c = 0; c < 4; ++c) {
            if (c < 3) cpa_wait<1>(); else cpa_wait<0>();
            __syncthreads();
            compute(c % 3, sb + SO_W2H, sb + SO_W2L, c * 8 + khalf * 2);
            if (c + 2 < 4) issue2(c + 2, (c + 2) % 3);
        }
        storeDp();
        __syncthreads();
        {   // sample epilogue: one (b, n) per thread
            int b = e2_b;
            float pm = 0.f, ps = 0.f;
            #pragma unroll
            for (int kp = 0; kp < 4; ++kp) {
                pm += Dp[kp * 1152 + b * 18 + e2_j];
                ps += Dp[kp * 1152 + b * 18 + 8 + e2_j];
            }
            float mu = fminf(fmaxf(pm, 1e-6f), 1e6f);
            float sd = fmaxf(softplus(ps), 1e-6f);
            int n = n0_2 + e2_j;
            float smp = fmaf(eps_pre, sd, mu);
            size_t o = (size_t)b * 262656 + (size_t)(s + 1) * 512 + n;
            out[muB + o] = mu;
            out[sdB + o] = sd;
            if (isH) {
                out[O_HID + (size_t)b * 262144 + (size_t)s * 512 + n] = smp;
                __nv_bfloat16 hh2 = __float2bfloat16(smp);
                g_hh[b * 512 + n] = hh2;
                g_hl[b * 512 + n] = __float2bfloat16(smp - __bfloat162float(hh2));
            } else {
                g_cs[b * 512 + n] = smp;
            }
            if (s == Sn - 1) out[tB + (size_t)b * 512 + n] = smp;
        }
        grid_bar(gen);
    }
}

extern "C" void kernel_launch(void* const* d_in, const int* in_sizes, int n_in,
                              void* d_out, int out_size) {
    (void)in_sizes; (void)n_in; (void)out_size;
    const float* x    = (const float*)d_in[0];
    const float* W_ih = (const float*)d_in[1];
    const float* W_hh = (const float*)d_in[2];
    const float* b_ih = (const float*)d_in[3];
    const float* b_hh = (const float*)d_in[4];
    const float* W_hg = (const float*)d_in[5];
    const float* W_cg = (const float*)d_in[6];
    const float* eps_h = (const float*)d_in[7];
    const float* eps_c = (const float*)d_in[8];
    float* out = (float*)d_out;

    xsplit_kernel<<<65536, 256>>>(x);

    cudaFuncSetAttribute(precomp, cudaFuncAttributeMaxDynamicSharedMemorySize, SMEM_P);
    precomp<<<dim3(128, 8), 512, SMEM_P>>>(W_ih);

    cudaFuncSetAttribute(rglstm, cudaFuncAttributeMaxDynamicSharedMemorySize, SMEM_BYTES);
    rglstm<<<NBLK, NTHR, SMEM_BYTES>>>(W_ih, W_hh, b_ih, b_hh,
                                       W_hg, W_cg, eps_h, eps_c, out);
}